// round 16
// baseline (speedup 1.0000x reference)
#include <cuda_runtime.h>
#include <cstdint>

// Problem constants
#define N_PIXT  131072      // 32 * 64 * 64 pixels (B*H*W)
#define KC      512
#define DD      64
#define TPB     128
#define PIX_PER_BLK 256
#define NBLK    (N_PIXT / PIX_PER_BLK)   // 512
#define MARGIN  4e-3f
#define CAND_CAP 32

// Output layout (float32 concat in reference return order):
#define OFF_LOSS 0ULL
#define OFF_Q    1ULL
#define OFF_PERP 8388609ULL
#define OFF_ENC  8388610ULL
#define OFF_IDX  75497474ULL

struct Scratch { int counts[KC]; double sumsq; int ticket; };
__device__ Scratch g_s;

// smem byte offsets
enum : uint32_t {
    SM_E8   = 0,        // int8 codebook: 512 x 16 u32 = 32768
    SM_SE   = 32768,    // 512 f32 = 2048
    SM_CAND = 34816,    // 256 pix x 32 u16 = 16384
    SM_IDX  = 51200,    // 256 i32 = 1024
    SM_TOT  = 52224
};

// ---------- packed f32x2 helpers ----------
__device__ __forceinline__ unsigned long long fma2(unsigned long long a,
                                                   unsigned long long b,
                                                   unsigned long long c) {
    unsigned long long d;
    asm("fma.rn.f32x2 %0, %1, %2, %3;" : "=l"(d) : "l"(a), "l"(b), "l"(c));
    return d;
}
__device__ __forceinline__ unsigned long long pack2(float lo, float hi) {
    unsigned long long d;
    asm("mov.b64 %0, {%1, %2};" : "=l"(d) : "f"(lo), "f"(hi));
    return d;
}
__device__ __forceinline__ void unpack2(unsigned long long v, float& lo, float& hi) {
    asm("mov.b64 {%0, %1}, %2;" : "=f"(lo), "=f"(hi) : "l"(v));
}
__device__ __forceinline__ uint32_t packb(int a, int b, int c, int d) {
    return (uint32_t)(a & 0xFF) | ((uint32_t)(b & 0xFF) << 8) |
           ((uint32_t)(c & 0xFF) << 16) | ((uint32_t)(d & 0xFF) << 24);
}

// Exact distance, bit-identical to the R8-passing kernel's chain.
__device__ __forceinline__ float exact_dist(const unsigned long long* zp, float sumz,
                                            float se, const float* erow) {
    unsigned long long a0 = 0ULL, a1 = 0ULL;
    const float4* e4 = (const float4*)erow;
#pragma unroll
    for (int i = 0; i < 16; i++) {
        float4 v = e4[i];
        a0 = fma2(zp[2 * i],     pack2(v.x, v.y), a0);
        a1 = fma2(zp[2 * i + 1], pack2(v.z, v.w), a1);
    }
    float p0, p1, p2, p3;
    unpack2(a0, p0, p1);
    unpack2(a1, p2, p3);
    float dot = __fadd_rn(__fadd_rn(p0, p1), __fadd_rn(p2, p3));
    return __fsub_rn(__fadd_rn(sumz, se), __fmul_rn(2.0f, dot));
}

extern __shared__ float4 smem4[];

__global__ __launch_bounds__(TPB, 4) void vq_dp4(const float* __restrict__ z,
                                                 const float* __restrict__ emb,
                                                 float* __restrict__ out) {
    char* smem = (char*)smem4;
    uint32_t*       s_e8 = (uint32_t*)(smem + SM_E8);
    float*          s_se = (float*)   (smem + SM_SE);
    unsigned short* s_cd = (unsigned short*)(smem + SM_CAND);
    int*            s_if = (int*)     (smem + SM_IDX);
    __shared__ double s_red[TPB];

    const int tid = threadIdx.x;
    const int wid = tid >> 5, lane = tid & 31;

    // ---- stage + quantize codebook, exact se (sequential ref order) ----
    for (int r = tid; r < KC; r += TPB) {
        const float4* er = (const float4*)(emb + r * DD);
        uint32_t* dst = s_e8 + r * 16;
        float se = 0.f;
#pragma unroll
        for (int i = 0; i < 16; i++) {
            float4 v = er[i];
            se = __fadd_rn(se, __fmul_rn(v.x, v.x));
            se = __fadd_rn(se, __fmul_rn(v.y, v.y));
            se = __fadd_rn(se, __fmul_rn(v.z, v.z));
            se = __fadd_rn(se, __fmul_rn(v.w, v.w));
            dst[i] = packb(__float2int_rn(v.x * 65024.0f), __float2int_rn(v.y * 65024.0f),
                           __float2int_rn(v.z * 65024.0f), __float2int_rn(v.w * 65024.0f));
        }
        s_se[r] = se;
    }
    __syncthreads();

    // ---- load + quantize z for 2 pixels; exact sumz (ref order) ----
    const int n0 = blockIdx.x * PIX_PER_BLK + tid;
    const int n1 = n0 + TPB;
    const size_t zb0 = (size_t)(n0 >> 12) * 262144 + (size_t)(n0 & 4095);
    const size_t zb1 = (size_t)(n1 >> 12) * 262144 + (size_t)(n1 & 4095);
    const float* zg0 = z + zb0;
    const float* zg1 = z + zb1;

    uint32_t q0[16], q1[16];
    float sumz0, sumz1, cp0, cp1;
    {
        float t[64];
        float sz = 0.f, mx = 0.f;
#pragma unroll
        for (int i = 0; i < 32; i++) {
            float a = zg0[(2 * i) * 4096];
            float c = zg0[(2 * i + 1) * 4096];
            sz = __fadd_rn(sz, __fmul_rn(a, a));
            sz = __fadd_rn(sz, __fmul_rn(c, c));
            mx = fmaxf(mx, fmaxf(fabsf(a), fabsf(c)));
            t[2 * i] = a; t[2 * i + 1] = c;
        }
        sumz0 = sz;
        float zs = (mx > 0.f) ? 127.0f / mx : 0.f;
        cp0 = (mx > 0.f) ? -2.0f * (mx / 127.0f) * (1.0f / 65024.0f) : 0.f;
#pragma unroll
        for (int w = 0; w < 16; w++)
            q0[w] = packb(__float2int_rn(t[4 * w] * zs),     __float2int_rn(t[4 * w + 1] * zs),
                          __float2int_rn(t[4 * w + 2] * zs), __float2int_rn(t[4 * w + 3] * zs));
    }
    {
        float t[64];
        float sz = 0.f, mx = 0.f;
#pragma unroll
        for (int i = 0; i < 32; i++) {
            float a = zg1[(2 * i) * 4096];
            float c = zg1[(2 * i + 1) * 4096];
            sz = __fadd_rn(sz, __fmul_rn(a, a));
            sz = __fadd_rn(sz, __fmul_rn(c, c));
            mx = fmaxf(mx, fmaxf(fabsf(a), fabsf(c)));
            t[2 * i] = a; t[2 * i + 1] = c;
        }
        sumz1 = sz;
        float zs = (mx > 0.f) ? 127.0f / mx : 0.f;
        cp1 = (mx > 0.f) ? -2.0f * (mx / 127.0f) * (1.0f / 65024.0f) : 0.f;
#pragma unroll
        for (int w = 0; w < 16; w++)
            q1[w] = packb(__float2int_rn(t[4 * w] * zs),     __float2int_rn(t[4 * w + 1] * zs),
                          __float2int_rn(t[4 * w + 2] * zs), __float2int_rn(t[4 * w + 3] * zs));
    }

    // ---- dp4a screen: 4 independent accum chains/pixel, prefetched rows,
    //      branchless candidate collection ----
    float best0 = 3.4e38f, best1 = 3.4e38f;
    float lim0 = 3.4e38f, lim1 = 3.4e38f;
    int bk0 = 0, bk1 = 0, c0 = 0, c1 = 0;
    unsigned short* cd0 = s_cd + tid * CAND_CAP;
    unsigned short* cd1 = s_cd + (tid + TPB) * CAND_CAP;
    const uint4* e8 = (const uint4*)s_e8;

    uint4 w0 = e8[0], w1 = e8[1], w2 = e8[2], w3 = e8[3];
#pragma unroll 2
    for (int k = 0; k < KC; k++) {
        // prefetch next row (wraps harmlessly at k=511)
        const uint4* nr = e8 + ((k + 1) & (KC - 1)) * 4;
        uint4 x0 = nr[0], x1 = nr[1], x2 = nr[2], x3 = nr[3];
        const float se = s_se[k];

        int a0 = 0, a1 = 0, a2 = 0, a3 = 0;      // pixel0: 4 chains of depth 4
        int b0 = 0, b1 = 0, b2 = 0, b3 = 0;      // pixel1
        a0 = __dp4a((int)w0.x, (int)q0[0],  a0); b0 = __dp4a((int)w0.x, (int)q1[0],  b0);
        a1 = __dp4a((int)w0.y, (int)q0[1],  a1); b1 = __dp4a((int)w0.y, (int)q1[1],  b1);
        a2 = __dp4a((int)w0.z, (int)q0[2],  a2); b2 = __dp4a((int)w0.z, (int)q1[2],  b2);
        a3 = __dp4a((int)w0.w, (int)q0[3],  a3); b3 = __dp4a((int)w0.w, (int)q1[3],  b3);
        a0 = __dp4a((int)w1.x, (int)q0[4],  a0); b0 = __dp4a((int)w1.x, (int)q1[4],  b0);
        a1 = __dp4a((int)w1.y, (int)q0[5],  a1); b1 = __dp4a((int)w1.y, (int)q1[5],  b1);
        a2 = __dp4a((int)w1.z, (int)q0[6],  a2); b2 = __dp4a((int)w1.z, (int)q1[6],  b2);
        a3 = __dp4a((int)w1.w, (int)q0[7],  a3); b3 = __dp4a((int)w1.w, (int)q1[7],  b3);
        a0 = __dp4a((int)w2.x, (int)q0[8],  a0); b0 = __dp4a((int)w2.x, (int)q1[8],  b0);
        a1 = __dp4a((int)w2.y, (int)q0[9],  a1); b1 = __dp4a((int)w2.y, (int)q1[9],  b1);
        a2 = __dp4a((int)w2.z, (int)q0[10], a2); b2 = __dp4a((int)w2.z, (int)q1[10], b2);
        a3 = __dp4a((int)w2.w, (int)q0[11], a3); b3 = __dp4a((int)w2.w, (int)q1[11], b3);
        a0 = __dp4a((int)w3.x, (int)q0[12], a0); b0 = __dp4a((int)w3.x, (int)q1[12], b0);
        a1 = __dp4a((int)w3.y, (int)q0[13], a1); b1 = __dp4a((int)w3.y, (int)q1[13], b1);
        a2 = __dp4a((int)w3.z, (int)q0[14], a2); b2 = __dp4a((int)w3.z, (int)q1[14], b2);
        a3 = __dp4a((int)w3.w, (int)q0[15], a3); b3 = __dp4a((int)w3.w, (int)q1[15], b3);

        int d0 = (a0 + a1) + (a2 + a3);
        int d1 = (b0 + b1) + (b2 + b3);
        float s0 = __fmaf_rn((float)d0, cp0, se);
        float s1 = __fmaf_rn((float)d1, cp1, se);

        // branchless collect + best update (ascending-k, strict <)
        bool t0 = s0 < lim0;
        bool t1 = s1 < lim1;
        if (t0) cd0[c0 & (CAND_CAP - 1)] = (unsigned short)k;
        if (t1) cd1[c1 & (CAND_CAP - 1)] = (unsigned short)k;
        c0 += t0; c1 += t1;
        bool nb0 = s0 < best0;
        bool nb1 = s1 < best1;
        best0 = nb0 ? s0 : best0;  bk0 = nb0 ? k : bk0;
        best1 = nb1 ? s1 : best1;  bk1 = nb1 ? k : bk1;
        lim0 = best0 + MARGIN;
        lim1 = best1 + MARGIN;

        w0 = x0; w1 = x1; w2 = x2; w3 = x3;
    }
    if (c0 > CAND_CAP) c0 = CAND_CAP;
    if (c1 > CAND_CAP) c1 = CAND_CAP;

    // ---- per-pixel rescreen + outputs (sequential to cap registers) ----
    float lsum = 0.f;
#pragma unroll 1
    for (int pp = 0; pp < 2; pp++) {
        const float* zg  = pp ? zg1 : zg0;
        const size_t zb  = pp ? zb1 : zb0;
        const int    n   = pp ? n1 : n0;
        const float  sumz = pp ? sumz1 : sumz0;
        const float  bestv = pp ? best1 : best0;
        const float  cp = pp ? cp1 : cp0;
        const uint32_t* q = pp ? q1 : q0;
        const unsigned short* cd = pp ? cd1 : cd0;
        const int    cnt = pp ? c1 : c0;
        int bk = pp ? bk1 : bk0;

        // reload z as packed pairs (identical bits -> identical chain)
        unsigned long long zp[32];
#pragma unroll
        for (int i = 0; i < 32; i++)
            zp[i] = pack2(zg[(2 * i) * 4096], zg[(2 * i + 1) * 4096]);

        if (cnt > 1) {
            const float lim = bestv + MARGIN;
            float bex = 3.4e38f;
            int bkx = bk;
            for (int i = 0; i < cnt; i++) {
                const int k = cd[i];
                // cheap filter: recompute approx score vs final best
                const uint4* r = (const uint4*)s_e8 + k * 4;
                uint4 v0 = r[0], v1 = r[1], v2 = r[2], v3 = r[3];
                int d = 0;
                d = __dp4a((int)v0.x, (int)q[0],  d); d = __dp4a((int)v0.y, (int)q[1],  d);
                d = __dp4a((int)v0.z, (int)q[2],  d); d = __dp4a((int)v0.w, (int)q[3],  d);
                d = __dp4a((int)v1.x, (int)q[4],  d); d = __dp4a((int)v1.y, (int)q[5],  d);
                d = __dp4a((int)v1.z, (int)q[6],  d); d = __dp4a((int)v1.w, (int)q[7],  d);
                d = __dp4a((int)v2.x, (int)q[8],  d); d = __dp4a((int)v2.y, (int)q[9],  d);
                d = __dp4a((int)v2.z, (int)q[10], d); d = __dp4a((int)v2.w, (int)q[11], d);
                d = __dp4a((int)v3.x, (int)q[12], d); d = __dp4a((int)v3.y, (int)q[13], d);
                d = __dp4a((int)v3.z, (int)q[14], d); d = __dp4a((int)v3.w, (int)q[15], d);
                float s = __fmaf_rn((float)d, cp, s_se[k]);
                if (s >= lim) continue;
                float dist = exact_dist(zp, sumz, s_se[k], emb + k * DD);
                if (dist < bex) { bex = dist; bkx = k; }
            }
            bk = bkx;
        }

        s_if[pp * TPB + tid] = bk;
        out[OFF_IDX + (size_t)n] = (float)bk;
        atomicAdd(&g_s.counts[bk], 1);

        // quantized_st = fl(z + fl(q - z)), accumulate (q - z)^2  (R8 chain)
        float* qout = out + OFF_Q + zb;
        const float2* er2 = (const float2*)(emb + bk * DD);
#pragma unroll
        for (int i = 0; i < 32; i++) {
            float zlo, zhi;
            unpack2(zp[i], zlo, zhi);
            float2 e = er2[i];
            float d0 = __fsub_rn(e.x, zlo);
            float d1 = __fsub_rn(e.y, zhi);
            lsum += d0 * d0 + d1 * d1;
            qout[(2 * i) * 4096]     = __fadd_rn(zlo, d0);
            qout[(2 * i + 1) * 4096] = __fadd_rn(zhi, d1);
        }
    }

    // ---- block-reduce squared error (double), one atomic per block ----
    s_red[tid] = (double)lsum;
    __syncthreads();                 // also publishes s_if
#pragma unroll
    for (int off = 64; off > 0; off >>= 1) {
        if (tid < off) s_red[tid] += s_red[tid + off];
        __syncthreads();
    }
    if (tid == 0) atomicAdd(&g_s.sumsq, s_red[0]);

    // ---- cooperative one-hot writes (float2: OFF_ENC is 8B-aligned) ----
    const size_t enc_base = OFF_ENC + (size_t)(blockIdx.x * PIX_PER_BLK) * KC;
    for (int r = wid * 64; r < wid * 64 + 64; r++) {
        const int target = s_if[r];
        float2* rowp = (float2*)(out + enc_base + (size_t)r * KC);
#pragma unroll
        for (int j = lane; j < 256; j += 32) {
            int cc = j * 2;
            float2 v;
            v.x = (cc     == target) ? 1.f : 0.f;
            v.y = (cc + 1 == target) ? 1.f : 0.f;
            rowp[j] = v;
        }
    }

    // ---- last block finalizes loss + perplexity ----
    __shared__ int s_last;
    __threadfence();
    __syncthreads();
    if (tid == 0) s_last = (atomicAdd(&g_s.ticket, 1) == NBLK - 1) ? 1 : 0;
    __syncthreads();
    if (s_last) {
        __threadfence();
        double t = 0.0;
        for (int r = tid; r < KC; r += TPB) {
            float pf = (float)g_s.counts[r] * (1.0f / 131072.0f);
            t += (double)(pf * logf(pf + 1e-10f));
        }
        s_red[tid] = t;
        __syncthreads();
#pragma unroll
        for (int off = 64; off > 0; off >>= 1) {
            if (tid < off) s_red[tid] += s_red[tid + off];
            __syncthreads();
        }
        if (tid == 0) {
            out[OFF_PERP] = expf((float)(-s_red[0]));
            double m = g_s.sumsq / 8388608.0;
            float mf = (float)m;
            out[OFF_LOSS] = __fadd_rn(mf, __fmul_rn(0.25f, mf));
        }
    }
}

extern "C" void kernel_launch(void* const* d_in, const int* in_sizes, int n_in,
                              void* d_out, int out_size) {
    const float* z   = (const float*)d_in[0];   // latent_z [32,64,64,64]
    const float* emb = (const float*)d_in[1];   // embedding [512,64]
    float* out = (float*)d_out;

    void* sp = nullptr;
    cudaGetSymbolAddress(&sp, g_s);
    cudaMemsetAsync(sp, 0, sizeof(Scratch), 0);

    cudaFuncSetAttribute(vq_dp4, cudaFuncAttributeMaxDynamicSharedMemorySize, SM_TOT);
    vq_dp4<<<NBLK, TPB, SM_TOT>>>(z, emb, out);
}

// round 17
// speedup vs baseline: 1.2644x; 1.2644x over previous
#include <cuda_runtime.h>
#include <cstdint>

// Problem constants
#define N_PIXT  131072      // 32 * 64 * 64 pixels (B*H*W)
#define KC      512
#define DD      64
#define TPB     256
#define PIX_PER_BLK 512
#define NBLK    (N_PIXT / PIX_PER_BLK)   // 256
#define MARGIN  1.5e-3f
#define CAND_CAP 32

// Output layout (float32 concat in reference return order):
#define OFF_LOSS 0ULL
#define OFF_Q    1ULL
#define OFF_PERP 8388609ULL
#define OFF_ENC  8388610ULL
#define OFF_IDX  75497474ULL

struct Scratch { int counts[KC]; double sumsq; int ticket; };
__device__ Scratch g_s;

// smem byte offsets
enum : uint32_t {
    SM_E8   = 0,        // int8 codebook: 512 x 16 u32 = 32768
    SM_SE   = 32768,    // 512 f32 = 2048
    SM_CAND = 34816,    // 512 pix x 32 u16 = 32768
    SM_TOT  = 67584
};

// ---------- packed f32x2 helpers ----------
__device__ __forceinline__ unsigned long long fma2(unsigned long long a,
                                                   unsigned long long b,
                                                   unsigned long long c) {
    unsigned long long d;
    asm("fma.rn.f32x2 %0, %1, %2, %3;" : "=l"(d) : "l"(a), "l"(b), "l"(c));
    return d;
}
__device__ __forceinline__ unsigned long long pack2(float lo, float hi) {
    unsigned long long d;
    asm("mov.b64 %0, {%1, %2};" : "=l"(d) : "f"(lo), "f"(hi));
    return d;
}
__device__ __forceinline__ void unpack2(unsigned long long v, float& lo, float& hi) {
    asm("mov.b64 {%0, %1}, %2;" : "=f"(lo), "=f"(hi) : "l"(v));
}
__device__ __forceinline__ uint32_t packb(int a, int b, int c, int d) {
    return (uint32_t)(a & 0xFF) | ((uint32_t)(b & 0xFF) << 8) |
           ((uint32_t)(c & 0xFF) << 16) | ((uint32_t)(d & 0xFF) << 24);
}

// Exact distance, bit-identical to the R8-passing kernel's chain.
__device__ __forceinline__ float exact_dist(const unsigned long long* zp, float sumz,
                                            float se, const float* erow) {
    unsigned long long a0 = 0ULL, a1 = 0ULL;
    const float4* e4 = (const float4*)erow;
#pragma unroll
    for (int i = 0; i < 16; i++) {
        float4 v = e4[i];
        a0 = fma2(zp[2 * i],     pack2(v.x, v.y), a0);
        a1 = fma2(zp[2 * i + 1], pack2(v.z, v.w), a1);
    }
    float p0, p1, p2, p3;
    unpack2(a0, p0, p1);
    unpack2(a1, p2, p3);
    float dot = __fadd_rn(__fadd_rn(p0, p1), __fadd_rn(p2, p3));
    return __fsub_rn(__fadd_rn(sumz, se), __fmul_rn(2.0f, dot));
}

extern __shared__ float4 smem4[];

__global__ __launch_bounds__(TPB, 2) void vq_dp4(const float* __restrict__ z,
                                                 const float* __restrict__ emb,
                                                 float* __restrict__ out) {
    char* smem = (char*)smem4;
    uint32_t*       s_e8 = (uint32_t*)(smem + SM_E8);
    float*          s_se = (float*)   (smem + SM_SE);
    unsigned short* s_cd = (unsigned short*)(smem + SM_CAND);

    const int tid = threadIdx.x;
    const int wid = tid >> 5, lane = tid & 31;

    // ---- stage + quantize codebook, exact se (sequential ref order) ----
    for (int r = tid; r < KC; r += TPB) {
        const float4* er = (const float4*)(emb + r * DD);
        uint32_t* dst = s_e8 + r * 16;
        float se = 0.f;
#pragma unroll
        for (int i = 0; i < 16; i++) {
            float4 v = er[i];
            se = __fadd_rn(se, __fmul_rn(v.x, v.x));
            se = __fadd_rn(se, __fmul_rn(v.y, v.y));
            se = __fadd_rn(se, __fmul_rn(v.z, v.z));
            se = __fadd_rn(se, __fmul_rn(v.w, v.w));
            dst[i] = packb(__float2int_rn(v.x * 65024.0f), __float2int_rn(v.y * 65024.0f),
                           __float2int_rn(v.z * 65024.0f), __float2int_rn(v.w * 65024.0f));
        }
        s_se[r] = se;
    }
    __syncthreads();

    // ---- load + quantize z for 2 pixels; exact sumz (ref order) ----
    const int n0 = blockIdx.x * PIX_PER_BLK + tid;
    const int n1 = n0 + TPB;
    const size_t zb0 = (size_t)(n0 >> 12) * 262144 + (size_t)(n0 & 4095);
    const size_t zb1 = (size_t)(n1 >> 12) * 262144 + (size_t)(n1 & 4095);
    const float* zg0 = z + zb0;
    const float* zg1 = z + zb1;

    uint32_t q0[16], q1[16];
    float sumz0, sumz1, cp0, cp1;
    {
        float t[64];
        float sz = 0.f, mx = 0.f;
#pragma unroll
        for (int i = 0; i < 32; i++) {
            float a = zg0[(2 * i) * 4096];
            float c = zg0[(2 * i + 1) * 4096];
            sz = __fadd_rn(sz, __fmul_rn(a, a));
            sz = __fadd_rn(sz, __fmul_rn(c, c));
            mx = fmaxf(mx, fmaxf(fabsf(a), fabsf(c)));
            t[2 * i] = a; t[2 * i + 1] = c;
        }
        sumz0 = sz;
        float zs = (mx > 0.f) ? 127.0f / mx : 0.f;
        cp0 = (mx > 0.f) ? -2.0f * (mx / 127.0f) * (1.0f / 65024.0f) : 0.f;
#pragma unroll
        for (int w = 0; w < 16; w++)
            q0[w] = packb(__float2int_rn(t[4 * w] * zs),     __float2int_rn(t[4 * w + 1] * zs),
                          __float2int_rn(t[4 * w + 2] * zs), __float2int_rn(t[4 * w + 3] * zs));
    }
    {
        float t[64];
        float sz = 0.f, mx = 0.f;
#pragma unroll
        for (int i = 0; i < 32; i++) {
            float a = zg1[(2 * i) * 4096];
            float c = zg1[(2 * i + 1) * 4096];
            sz = __fadd_rn(sz, __fmul_rn(a, a));
            sz = __fadd_rn(sz, __fmul_rn(c, c));
            mx = fmaxf(mx, fmaxf(fabsf(a), fabsf(c)));
            t[2 * i] = a; t[2 * i + 1] = c;
        }
        sumz1 = sz;
        float zs = (mx > 0.f) ? 127.0f / mx : 0.f;
        cp1 = (mx > 0.f) ? -2.0f * (mx / 127.0f) * (1.0f / 65024.0f) : 0.f;
#pragma unroll
        for (int w = 0; w < 16; w++)
            q1[w] = packb(__float2int_rn(t[4 * w] * zs),     __float2int_rn(t[4 * w + 1] * zs),
                          __float2int_rn(t[4 * w + 2] * zs), __float2int_rn(t[4 * w + 3] * zs));
    }

    // ---- dp4a screen: 4 independent accum chains/pixel, prefetched rows,
    //      branchless candidate collection ----
    float best0 = 3.4e38f, best1 = 3.4e38f;
    float lim0 = 3.4e38f, lim1 = 3.4e38f;
    int bk0 = 0, bk1 = 0, c0 = 0, c1 = 0;
    unsigned short* cd0 = s_cd + tid * CAND_CAP;
    unsigned short* cd1 = s_cd + (tid + TPB) * CAND_CAP;
    const uint4* e8 = (const uint4*)s_e8;

    uint4 w0 = e8[0], w1 = e8[1], w2 = e8[2], w3 = e8[3];
#pragma unroll 2
    for (int k = 0; k < KC; k++) {
        // prefetch next row (wraps harmlessly at k=511)
        const uint4* nr = e8 + ((k + 1) & (KC - 1)) * 4;
        uint4 x0 = nr[0], x1 = nr[1], x2 = nr[2], x3 = nr[3];
        const float se = s_se[k];

        int a0 = 0, a1 = 0, a2 = 0, a3 = 0;      // pixel0: 4 chains of depth 4
        int b0 = 0, b1 = 0, b2 = 0, b3 = 0;      // pixel1
        a0 = __dp4a((int)w0.x, (int)q0[0],  a0); b0 = __dp4a((int)w0.x, (int)q1[0],  b0);
        a1 = __dp4a((int)w0.y, (int)q0[1],  a1); b1 = __dp4a((int)w0.y, (int)q1[1],  b1);
        a2 = __dp4a((int)w0.z, (int)q0[2],  a2); b2 = __dp4a((int)w0.z, (int)q1[2],  b2);
        a3 = __dp4a((int)w0.w, (int)q0[3],  a3); b3 = __dp4a((int)w0.w, (int)q1[3],  b3);
        a0 = __dp4a((int)w1.x, (int)q0[4],  a0); b0 = __dp4a((int)w1.x, (int)q1[4],  b0);
        a1 = __dp4a((int)w1.y, (int)q0[5],  a1); b1 = __dp4a((int)w1.y, (int)q1[5],  b1);
        a2 = __dp4a((int)w1.z, (int)q0[6],  a2); b2 = __dp4a((int)w1.z, (int)q1[6],  b2);
        a3 = __dp4a((int)w1.w, (int)q0[7],  a3); b3 = __dp4a((int)w1.w, (int)q1[7],  b3);
        a0 = __dp4a((int)w2.x, (int)q0[8],  a0); b0 = __dp4a((int)w2.x, (int)q1[8],  b0);
        a1 = __dp4a((int)w2.y, (int)q0[9],  a1); b1 = __dp4a((int)w2.y, (int)q1[9],  b1);
        a2 = __dp4a((int)w2.z, (int)q0[10], a2); b2 = __dp4a((int)w2.z, (int)q1[10], b2);
        a3 = __dp4a((int)w2.w, (int)q0[11], a3); b3 = __dp4a((int)w2.w, (int)q1[11], b3);
        a0 = __dp4a((int)w3.x, (int)q0[12], a0); b0 = __dp4a((int)w3.x, (int)q1[12], b0);
        a1 = __dp4a((int)w3.y, (int)q0[13], a1); b1 = __dp4a((int)w3.y, (int)q1[13], b1);
        a2 = __dp4a((int)w3.z, (int)q0[14], a2); b2 = __dp4a((int)w3.z, (int)q1[14], b2);
        a3 = __dp4a((int)w3.w, (int)q0[15], a3); b3 = __dp4a((int)w3.w, (int)q1[15], b3);

        int d0 = (a0 + a1) + (a2 + a3);
        int d1 = (b0 + b1) + (b2 + b3);
        float s0 = __fmaf_rn((float)d0, cp0, se);
        float s1 = __fmaf_rn((float)d1, cp1, se);

        // branchless collect + best update (ascending-k, strict <)
        bool t0 = s0 < lim0;
        bool t1 = s1 < lim1;
        if (t0) cd0[c0 & (CAND_CAP - 1)] = (unsigned short)k;
        if (t1) cd1[c1 & (CAND_CAP - 1)] = (unsigned short)k;
        c0 += t0; c1 += t1;
        bool nb0 = s0 < best0;
        bool nb1 = s1 < best1;
        best0 = nb0 ? s0 : best0;  bk0 = nb0 ? k : bk0;
        best1 = nb1 ? s1 : best1;  bk1 = nb1 ? k : bk1;
        lim0 = best0 + MARGIN;
        lim1 = best1 + MARGIN;

        w0 = x0; w1 = x1; w2 = x2; w3 = x3;
    }
    if (c0 > CAND_CAP) c0 = CAND_CAP;
    if (c1 > CAND_CAP) c1 = CAND_CAP;

    // ---- per-pixel exact rescreen + outputs (sequential to cap registers) ----
    float lsum = 0.f;
#pragma unroll 1
    for (int pp = 0; pp < 2; pp++) {
        const float* zg  = pp ? zg1 : zg0;
        const size_t zb  = pp ? zb1 : zb0;
        const int    n   = pp ? n1 : n0;
        const float  sumz = pp ? sumz1 : sumz0;
        const unsigned short* cd = pp ? cd1 : cd0;
        const int    cnt = pp ? c1 : c0;
        int bk = pp ? bk1 : bk0;

        // reload z as packed pairs (identical bits -> identical chain)
        unsigned long long zp[32];
#pragma unroll
        for (int i = 0; i < 32; i++)
            zp[i] = pack2(zg[(2 * i) * 4096], zg[(2 * i + 1) * 4096]);

        if (cnt > 1) {
            float bex = 3.4e38f;
            int bkx = 0;
            for (int i = 0; i < cnt; i++) {
                const int k = cd[i];
                float dist = exact_dist(zp, sumz, s_se[k], emb + k * DD);
                if (dist < bex) { bex = dist; bkx = k; }
            }
            bk = bkx;
        }
        if (pp) bk1 = bk; else bk0 = bk;

        out[OFF_IDX + (size_t)n] = (float)bk;
        atomicAdd(&g_s.counts[bk], 1);

        // quantized_st = fl(z + fl(q - z)), accumulate (q - z)^2  (R8 chain)
        float* qout = out + OFF_Q + zb;
        const float2* er2 = (const float2*)(emb + bk * DD);
#pragma unroll
        for (int i = 0; i < 32; i++) {
            float zlo, zhi;
            unpack2(zp[i], zlo, zhi);
            float2 e = er2[i];
            float d0 = __fsub_rn(e.x, zlo);
            float d1 = __fsub_rn(e.y, zhi);
            lsum += d0 * d0 + d1 * d1;
            qout[(2 * i) * 4096]     = __fadd_rn(zlo, d0);
            qout[(2 * i + 1) * 4096] = __fadd_rn(zhi, d1);
        }
    }

    // ---- warp-level sumsq reduce (double), one atomic per warp ----
    {
        double v = (double)lsum;
#pragma unroll
        for (int off = 16; off > 0; off >>= 1)
            v += __shfl_down_sync(0xFFFFFFFFu, v, off);
        if (lane == 0) atomicAdd(&g_s.sumsq, v);
    }

    // ---- one-hot encodings via shfl: warp writes its own lanes' 64 rows ----
    // rows for this warp: [blk*512 + wid*32, +32) (bk0) and [+TPB..] (bk1)
    {
        const size_t enc_base = OFF_ENC + (size_t)(blockIdx.x * PIX_PER_BLK) * KC;
#pragma unroll 1
        for (int pp = 0; pp < 2; pp++) {
            const int mybk = pp ? bk1 : bk0;
            const size_t row0 = (size_t)(pp * TPB + wid * 32);
#pragma unroll 1
            for (int r = 0; r < 32; r++) {
                const int target = __shfl_sync(0xFFFFFFFFu, mybk, r);
                float2* rowp = (float2*)(out + enc_base + (row0 + r) * KC);
#pragma unroll
                for (int j = lane; j < 256; j += 32) {
                    int cc = j * 2;
                    float2 v;
                    v.x = (cc     == target) ? 1.f : 0.f;
                    v.y = (cc + 1 == target) ? 1.f : 0.f;
                    rowp[j] = v;
                }
            }
        }
    }

    // ---- last block finalizes loss + perplexity ----
    __shared__ int s_last;
    __shared__ double s_fin[TPB];
    __threadfence();
    __syncthreads();
    if (tid == 0) s_last = (atomicAdd(&g_s.ticket, 1) == NBLK - 1) ? 1 : 0;
    __syncthreads();
    if (s_last) {
        __threadfence();
        double t = 0.0;
        for (int r = tid; r < KC; r += TPB) {
            float pf = (float)g_s.counts[r] * (1.0f / 131072.0f);
            t += (double)(pf * logf(pf + 1e-10f));
        }
        s_fin[tid] = t;
        __syncthreads();
#pragma unroll
        for (int off = 128; off > 0; off >>= 1) {
            if (tid < off) s_fin[tid] += s_fin[tid + off];
            __syncthreads();
        }
        if (tid == 0) {
            out[OFF_PERP] = expf((float)(-s_fin[0]));
            double m = g_s.sumsq / 8388608.0;
            float mf = (float)m;
            out[OFF_LOSS] = __fadd_rn(mf, __fmul_rn(0.25f, mf));
        }
    }
}

extern "C" void kernel_launch(void* const* d_in, const int* in_sizes, int n_in,
                              void* d_out, int out_size) {
    const float* z   = (const float*)d_in[0];   // latent_z [32,64,64,64]
    const float* emb = (const float*)d_in[1];   // embedding [512,64]
    float* out = (float*)d_out;

    void* sp = nullptr;
    cudaGetSymbolAddress(&sp, g_s);
    cudaMemsetAsync(sp, 0, sizeof(Scratch), 0);

    cudaFuncSetAttribute(vq_dp4, cudaFuncAttributeMaxDynamicSharedMemorySize, SM_TOT);
    vq_dp4<<<NBLK, TPB, SM_TOT>>>(z, emb, out);
}